// round 6
// baseline (speedup 1.0000x reference)
#include <cuda_runtime.h>

// Problem constants (fixed by the reference: B=32, M=4, D=196608)
constexpr int B_    = 32;
constexpr int M_    = 4;
constexpr int D_    = 196608;
constexpr int D4_   = D_ / 4;      // 49152 float4 per row
constexpr int BPG   = 24;          // blocks per group -> grid 768
constexpr int TPB   = 256;
constexpr int NWARP = TPB / 32;
constexpr int NSLOT = 36;          // 10 (st gram uptri) + 10 (sr gram uptri) + 16 (cross)
constexpr int GRID  = B_ * BPG;
constexpr int SEG   = D4_ / (BPG * NWARP);   // 256 float4 = 4KB contiguous per warp per row
constexpr int NIT   = SEG / 32;              // 8 iterations per warp

static_assert(SEG * BPG * NWARP == D4_, "segmentation must be exact");

// Static scratch: fixed-order two-pass reduction (deterministic, no float atomics)
__device__ float        g_partials[GRID * NSLOT];
__device__ unsigned int g_counter = 0;   // blocks-done counter; reset by finalizing block

__device__ __forceinline__ void accum36(float acc[NSLOT], const float4 a[4], const float4 c[4]) {
#pragma unroll
    for (int v = 0; v < 4; v++) {
        float x[4], y[4];
#pragma unroll
        for (int i = 0; i < 4; i++) {
            x[i] = reinterpret_cast<const float*>(&a[i])[v];
            y[i] = reinterpret_cast<const float*>(&c[i])[v];
        }
        int s = 0;
#pragma unroll
        for (int i = 0; i < 4; i++)
#pragma unroll
            for (int j = i; j < 4; j++) { acc[s] = fmaf(x[i], x[j], acc[s]); s++; }
#pragma unroll
        for (int i = 0; i < 4; i++)
#pragma unroll
            for (int j = i; j < 4; j++) { acc[s] = fmaf(y[i], y[j], acc[s]); s++; }
#pragma unroll
        for (int i = 0; i < 4; i++)
#pragma unroll
            for (int j = 0; j < 4; j++) { acc[s] = fmaf(x[i], y[j], acc[s]); s++; }
    }
}

__device__ __forceinline__ float kmean4(const float (&GA)[4][4],
                                        const float (&GB)[4][4],
                                        const float (&XY)[4][4],
                                        float w) {
    const float invD = 1.0f / (float)D_;   // sigma = 1
    float sum = 0.0f;
#pragma unroll
    for (int i = 0; i < 4; i++) {
#pragma unroll
        for (int j = 0; j < 4; j++) {
            float d2 = GA[i][i] + GB[j][j] - 2.0f * XY[i][j];
            d2 = fmaxf(d2, 1e-12f);
            float dist = sqrtf(d2) * invD;
            float e = -dist * w;
            e = fminf(fmaxf(e, -1e6f), 0.0f);
            sum += expf(e);
        }
    }
    return sum * (1.0f / 16.0f);
}

__global__ __launch_bounds__(TPB) void mmd_fused(const float* __restrict__ st,
                                                 const float* __restrict__ sr,
                                                 const float* __restrict__ wt,
                                                 const float* __restrict__ wtout,
                                                 float* __restrict__ out) {
    const int blk  = blockIdx.x;
    const int b    = blk / BPG;
    const int sub  = blk - b * BPG;
    const int warp = threadIdx.x >> 5;
    const int lane = threadIdx.x & 31;

    const float4* __restrict__ A0 = reinterpret_cast<const float4*>(st) + (size_t)(b * M_ + 0) * D4_;
    const float4* __restrict__ A1 = reinterpret_cast<const float4*>(st) + (size_t)(b * M_ + 1) * D4_;
    const float4* __restrict__ A2 = reinterpret_cast<const float4*>(st) + (size_t)(b * M_ + 2) * D4_;
    const float4* __restrict__ A3 = reinterpret_cast<const float4*>(st) + (size_t)(b * M_ + 3) * D4_;
    const float4* __restrict__ C0 = reinterpret_cast<const float4*>(sr) + (size_t)(b * M_ + 0) * D4_;
    const float4* __restrict__ C1 = reinterpret_cast<const float4*>(sr) + (size_t)(b * M_ + 1) * D4_;
    const float4* __restrict__ C2 = reinterpret_cast<const float4*>(sr) + (size_t)(b * M_ + 2) * D4_;
    const float4* __restrict__ C3 = reinterpret_cast<const float4*>(sr) + (size_t)(b * M_ + 3) * D4_;

    float acc[NSLOT];
#pragma unroll
    for (int s = 0; s < NSLOT; s++) acc[s] = 0.0f;

    // Contiguous per-warp segment: sequential 512B/iter streams -> DRAM row-buffer friendly.
    int k = (sub * NWARP + warp) * SEG + lane;

    // Software pipeline: keep next iteration's 8 loads in flight while computing current.
    float4 a[4], c[4];
    a[0] = __ldcs(A0 + k); a[1] = __ldcs(A1 + k); a[2] = __ldcs(A2 + k); a[3] = __ldcs(A3 + k);
    c[0] = __ldcs(C0 + k); c[1] = __ldcs(C1 + k); c[2] = __ldcs(C2 + k); c[3] = __ldcs(C3 + k);

#pragma unroll
    for (int it = 1; it < NIT; it++) {
        const int kn = k + 32;
        float4 an[4], cn[4];
        an[0] = __ldcs(A0 + kn); an[1] = __ldcs(A1 + kn); an[2] = __ldcs(A2 + kn); an[3] = __ldcs(A3 + kn);
        cn[0] = __ldcs(C0 + kn); cn[1] = __ldcs(C1 + kn); cn[2] = __ldcs(C2 + kn); cn[3] = __ldcs(C3 + kn);

        accum36(acc, a, c);

#pragma unroll
        for (int i = 0; i < 4; i++) { a[i] = an[i]; c[i] = cn[i]; }
        k = kn;
    }
    accum36(acc, a, c);

    // Warp tree reduction of all 36 accumulators
#pragma unroll
    for (int s = 0; s < NSLOT; s++) {
        float v = acc[s];
        v += __shfl_down_sync(0xffffffffu, v, 16);
        v += __shfl_down_sync(0xffffffffu, v, 8);
        v += __shfl_down_sync(0xffffffffu, v, 4);
        v += __shfl_down_sync(0xffffffffu, v, 2);
        v += __shfl_down_sync(0xffffffffu, v, 1);
        acc[s] = v;
    }

    __shared__ float sm[NWARP][NSLOT];
    if (lane == 0) {
#pragma unroll
        for (int s = 0; s < NSLOT; s++) sm[warp][s] = acc[s];
    }
    __syncthreads();

    if (threadIdx.x < NSLOT) {
        float t = 0.0f;
#pragma unroll
        for (int w = 0; w < NWARP; w++) t += sm[w][threadIdx.x];
        g_partials[blk * NSLOT + threadIdx.x] = t;
    }

    // ---- last-block-done election ----
    __shared__ unsigned int s_isLast;
    __threadfence();                       // make partials visible before counting
    __syncthreads();                       // ensure this block's store happened
    if (threadIdx.x == 0) {
        unsigned int old = atomicAdd(&g_counter, 1u);
        s_isLast = (old == (unsigned int)(GRID - 1)) ? 1u : 0u;
    }
    __syncthreads();
    if (!s_isLast) return;

    // ---- finalize (runs in exactly one block; partials are L2-hot) ----
    __shared__ float G[B_][NSLOT];
    __shared__ float lossS[B_];

    for (int g = warp; g < B_; g += NWARP) {
        for (int s = lane; s < NSLOT; s += 32) {
            float t = 0.0f;
#pragma unroll
            for (int kb = 0; kb < BPG; kb++) t += g_partials[(g * BPG + kb) * NSLOT + s];
            G[g][s] = t;
        }
    }
    __syncthreads();

    if (threadIdx.x < B_) {
        const int g = threadIdx.x;
        float Gst[4][4], Gsr[4][4], C[4][4];
        int s = 0;
#pragma unroll
        for (int i = 0; i < 4; i++)
#pragma unroll
            for (int j = i; j < 4; j++) { Gst[i][j] = G[g][s]; Gst[j][i] = G[g][s]; s++; }
#pragma unroll
        for (int i = 0; i < 4; i++)
#pragma unroll
            for (int j = i; j < 4; j++) { Gsr[i][j] = G[g][s]; Gsr[j][i] = G[g][s]; s++; }
#pragma unroll
        for (int i = 0; i < 4; i++)
#pragma unroll
            for (int j = 0; j < 4; j++) { C[i][j] = G[g][s]; s++; }

        const float w = wt[g];
        float m1 = kmean4(Gst, Gst, Gst, w);
        float m2 = kmean4(Gsr, Gsr, Gsr, w);
        float m3 = kmean4(Gst, Gsr, C, w);
        lossS[g] = wtout[g] * (m1 + m2 - 2.0f * m3);
    }
    __syncthreads();

    if (threadIdx.x == 0) {
        float t = 0.0f;
#pragma unroll
        for (int g = 0; g < B_; g++) t += lossS[g];
        out[0] = t * (1.0f / (float)B_);
        g_counter = 0;                     // reset for next graph replay
        __threadfence();
    }
}

extern "C" void kernel_launch(void* const* d_in, const int* in_sizes, int n_in,
                              void* d_out, int out_size) {
    const float* f_st  = (const float*)d_in[0];
    const float* f_sr  = (const float*)d_in[1];
    const float* wt    = (const float*)d_in[2];
    const float* wtout = (const float*)d_in[3];
    float* out = (float*)d_out;

    mmd_fused<<<GRID, TPB>>>(f_st, f_sr, wt, wtout, out);
}

// round 7
// speedup vs baseline: 1.1176x; 1.1176x over previous
#include <cuda_runtime.h>

// Problem constants (fixed by the reference: B=32, M=4, D=196608)
constexpr int B_    = 32;
constexpr int M_    = 4;
constexpr int D_    = 196608;
constexpr int D4_   = D_ / 4;      // 49152 float4 per row
constexpr int BPG   = 9;           // blocks per group (best measured streaming config)
constexpr int TPB   = 256;
constexpr int NWARP = TPB / 32;
constexpr int NSLOT = 36;          // 10 (st gram uptri) + 10 (sr gram uptri) + 16 (cross)
constexpr int GRID  = B_ * BPG;

// Static scratch: fixed-order reductions (deterministic; atomics only on int counters)
__device__ float        g_partials[GRID * NSLOT];
__device__ float        g_loss[B_];
__device__ unsigned int g_gcount[B_];    // per-group blocks-done counters (self-reset)
__device__ unsigned int g_fcount = 0;    // groups-finalized counter (self-reset)

__global__ __launch_bounds__(TPB) void mmd_fused(const float* __restrict__ st,
                                                 const float* __restrict__ sr,
                                                 const float* __restrict__ wt,
                                                 const float* __restrict__ wtout,
                                                 float* __restrict__ out) {
    const int blk  = blockIdx.x;
    const int b    = blk / BPG;
    const int sub  = blk - b * BPG;
    const int warp = threadIdx.x >> 5;
    const int lane = threadIdx.x & 31;

    const float4* __restrict__ A0 = reinterpret_cast<const float4*>(st) + (size_t)(b * M_ + 0) * D4_;
    const float4* __restrict__ A1 = reinterpret_cast<const float4*>(st) + (size_t)(b * M_ + 1) * D4_;
    const float4* __restrict__ A2 = reinterpret_cast<const float4*>(st) + (size_t)(b * M_ + 2) * D4_;
    const float4* __restrict__ A3 = reinterpret_cast<const float4*>(st) + (size_t)(b * M_ + 3) * D4_;
    const float4* __restrict__ C0 = reinterpret_cast<const float4*>(sr) + (size_t)(b * M_ + 0) * D4_;
    const float4* __restrict__ C1 = reinterpret_cast<const float4*>(sr) + (size_t)(b * M_ + 1) * D4_;
    const float4* __restrict__ C2 = reinterpret_cast<const float4*>(sr) + (size_t)(b * M_ + 2) * D4_;
    const float4* __restrict__ C3 = reinterpret_cast<const float4*>(sr) + (size_t)(b * M_ + 3) * D4_;

    float acc[NSLOT];
#pragma unroll
    for (int s = 0; s < NSLOT; s++) acc[s] = 0.0f;

#pragma unroll 2
    for (int k = sub * TPB + threadIdx.x; k < D4_; k += BPG * TPB) {
        // 8 independent 128-bit loads per iter -> deep MLP, coalesced
        float4 a[4];
        float4 c[4];
        a[0] = A0[k]; a[1] = A1[k]; a[2] = A2[k]; a[3] = A3[k];
        c[0] = C0[k]; c[1] = C1[k]; c[2] = C2[k]; c[3] = C3[k];

#pragma unroll
        for (int v = 0; v < 4; v++) {
            float x[4], y[4];
#pragma unroll
            for (int i = 0; i < 4; i++) {
                x[i] = reinterpret_cast<const float*>(&a[i])[v];
                y[i] = reinterpret_cast<const float*>(&c[i])[v];
            }
            int s = 0;
#pragma unroll
            for (int i = 0; i < 4; i++)
#pragma unroll
                for (int j = i; j < 4; j++) { acc[s] = fmaf(x[i], x[j], acc[s]); s++; }
#pragma unroll
            for (int i = 0; i < 4; i++)
#pragma unroll
                for (int j = i; j < 4; j++) { acc[s] = fmaf(y[i], y[j], acc[s]); s++; }
#pragma unroll
            for (int i = 0; i < 4; i++)
#pragma unroll
                for (int j = 0; j < 4; j++) { acc[s] = fmaf(x[i], y[j], acc[s]); s++; }
        }
    }

    // Warp tree reduction of all 36 accumulators
#pragma unroll
    for (int s = 0; s < NSLOT; s++) {
        float v = acc[s];
        v += __shfl_down_sync(0xffffffffu, v, 16);
        v += __shfl_down_sync(0xffffffffu, v, 8);
        v += __shfl_down_sync(0xffffffffu, v, 4);
        v += __shfl_down_sync(0xffffffffu, v, 2);
        v += __shfl_down_sync(0xffffffffu, v, 1);
        acc[s] = v;
    }

    __shared__ float sm[NWARP][NSLOT];
    if (lane == 0) {
#pragma unroll
        for (int s = 0; s < NSLOT; s++) sm[warp][s] = acc[s];
    }
    __syncthreads();

    if (threadIdx.x < NSLOT) {
        float t = 0.0f;
#pragma unroll
        for (int w = 0; w < NWARP; w++) t += sm[w][threadIdx.x];
        g_partials[blk * NSLOT + threadIdx.x] = t;
    }

    // ---- per-group last-block election (overlaps finalize with other groups' streaming) ----
    __shared__ unsigned int s_isGroupLast;
    __threadfence();                       // make this block's partials visible
    __syncthreads();
    if (threadIdx.x == 0) {
        unsigned int old = atomicAdd(&g_gcount[b], 1u);
        s_isGroupLast = (old == (unsigned int)(BPG - 1)) ? 1u : 0u;
    }
    __syncthreads();
    if (!s_isGroupLast) return;
    __threadfence();                       // acquire side: see all group partials

    // ---- group finalize: sum 9 partials per slot (36 threads, MLP=9) ----
    __shared__ float G[NSLOT];
    if (threadIdx.x < NSLOT) {
        const float* p = &g_partials[(b * BPG) * NSLOT + threadIdx.x];
        float t = 0.0f;
#pragma unroll
        for (int kb = 0; kb < BPG; kb++) t += p[kb * NSLOT];   // independent loads, fixed order
        G[threadIdx.x] = t;
    }
    __syncthreads();

    // 16 lanes of warp 0: entry (i,j) computes its 3 kernel terms; shfl-reduce.
    if (warp == 0) {
        const float w     = wt[b];
        const float invD  = 1.0f / (float)D_;   // sigma = 1
        float contrib = 0.0f;
        if (lane < 16) {
            const int i = lane >> 2;
            const int j = lane & 3;
            // slot index for upper-tri (i<=j): off(i) + (j-i), off = {0,4,7,9}
            auto tri = [](int r, int cc) { // r<=cc
                const int off[4] = {0, 4, 7, 9};
                return off[r] + (cc - r);
            };
            const int ij  = (i <= j) ? tri(i, j) : tri(j, i);
            const float gst_ii = G[tri(i, i)];
            const float gst_jj = G[tri(j, j)];
            const float gsr_ii = G[10 + tri(i, i)];
            const float gsr_jj = G[10 + tri(j, j)];
            const float gst_ij = G[ij];
            const float gsr_ij = G[10 + ij];
            const float c_ij   = G[20 + i * 4 + j];

            auto kterm = [&](float dii, float djj, float dij) {
                float d2 = fmaxf(dii + djj - 2.0f * dij, 1e-12f);
                float e  = -sqrtf(d2) * invD * w;
                e = fminf(fmaxf(e, -1e6f), 0.0f);
                return expf(e);
            };
            contrib = kterm(gst_ii, gst_jj, gst_ij)
                    + kterm(gsr_ii, gsr_jj, gsr_ij)
                    - 2.0f * kterm(gst_ii, gsr_jj, c_ij);
        }
        // fixed-order tree reduction over 16 lanes
        contrib += __shfl_down_sync(0xffffffffu, contrib, 8);
        contrib += __shfl_down_sync(0xffffffffu, contrib, 4);
        contrib += __shfl_down_sync(0xffffffffu, contrib, 2);
        contrib += __shfl_down_sync(0xffffffffu, contrib, 1);
        if (lane == 0) {
            g_loss[b] = wtout[b] * (contrib * (1.0f / 16.0f));
            g_gcount[b] = 0;               // reset for next graph replay
        }
    }

    // ---- global last-group election ----
    __shared__ unsigned int s_isGlobalLast;
    __threadfence();
    __syncthreads();
    if (threadIdx.x == 0) {
        unsigned int old = atomicAdd(&g_fcount, 1u);
        s_isGlobalLast = (old == (unsigned int)(B_ - 1)) ? 1u : 0u;
    }
    __syncthreads();
    if (!s_isGlobalLast) return;
    __threadfence();

    if (warp == 0) {
        float v = g_loss[lane];            // 32 independent loads (L2-hot)
        v += __shfl_down_sync(0xffffffffu, v, 16);
        v += __shfl_down_sync(0xffffffffu, v, 8);
        v += __shfl_down_sync(0xffffffffu, v, 4);
        v += __shfl_down_sync(0xffffffffu, v, 2);
        v += __shfl_down_sync(0xffffffffu, v, 1);
        if (lane == 0) {
            out[0] = v * (1.0f / (float)B_);
            g_fcount = 0;                  // reset for next graph replay
            __threadfence();
        }
    }
}

extern "C" void kernel_launch(void* const* d_in, const int* in_sizes, int n_in,
                              void* d_out, int out_size) {
    const float* f_st  = (const float*)d_in[0];
    const float* f_sr  = (const float*)d_in[1];
    const float* wt    = (const float*)d_in[2];
    const float* wtout = (const float*)d_in[3];
    float* out = (float*)d_out;

    mmd_fused<<<GRID, TPB>>>(f_st, f_sr, wt, wtout, out);
}